// round 1
// baseline (speedup 1.0000x reference)
#include <cuda_runtime.h>
#include <math.h>

#define HH 2048
#define WW 2048
#define NF 64
#define MAXD 12

// Per-frame node: split ratio + packed children (left | right<<8)
struct Node { float ratio; int child; };

__device__ int g_children[NF];

// Kernel 1: per-frame argmax over selection logits (first-max tie-break, matching jnp.argmax)
__global__ void k_children(const float* __restrict__ sel) {
    int i = threadIdx.x;
    if (i < NF) {
        const float* row = sel + i * 2 * NF;
        int l = 0; float bl = row[0];
        #pragma unroll 1
        for (int j = 1; j < NF; j++) { float v = row[j]; if (v > bl) { bl = v; l = j; } }
        int r = 0; float br = row[NF];
        #pragma unroll 1
        for (int j = 1; j < NF; j++) { float v = row[NF + j]; if (v > br) { br = v; r = j; } }
        g_children[i] = l | (r << 8);
    }
}

// Kernel 2: per-pixel BSP descent with block-uniform prefix.
// Block = 64x4 pixel tile (256 threads). Thread 0 descends the tree while the
// split line doesn't cross the tile (those levels are identical for every
// pixel in the tile); all threads resume per-pixel from the published state.
__global__ __launch_bounds__(256) void k_render(
    const float* __restrict__ colors,
    const float* __restrict__ ratios,
    float* __restrict__ out)
{
    __shared__ Node   s_node[NF];
    __shared__ float4 s_col[NF];
    __shared__ int    s_pre[6];   // idx, x0, y0, w, h, depth

    int t = threadIdx.y * 64 + threadIdx.x;
    if (t < NF) {
        Node n; n.ratio = ratios[t]; n.child = g_children[t];
        s_node[t] = n;
        s_col[t] = make_float4(colors[t * 3], colors[t * 3 + 1], colors[t * 3 + 2], 0.f);
    }
    __syncthreads();

    const int tx0 = blockIdx.x * 64;
    const int ty0 = blockIdx.y * 4;

    if (t == 0) {
        int idx = 0, x0 = 0, y0 = 0, w = WW, h = HH, d = 0;
        while (d < MAXD && w >= 2 && h >= 2) {
            Node n = s_node[idx];
            if (idx & 1) {
                int lw = max(1, (int)floorf((float)w * n.ratio));
                int xs = x0 + lw;
                if (tx0 + 64 <= xs)      { w = lw;           idx = n.child & 255; }
                else if (tx0 >= xs)      { x0 = xs; w -= lw; idx = n.child >> 8;  }
                else break;              // split line crosses tile -> per-pixel from here
            } else {
                int th = max(1, (int)floorf((float)h * n.ratio));
                int ys = y0 + th;
                if (ty0 + 4 <= ys)       { h = th;           idx = n.child & 255; }
                else if (ty0 >= ys)      { y0 = ys; h -= th; idx = n.child >> 8;  }
                else break;
            }
            d++;
        }
        s_pre[0] = idx; s_pre[1] = x0; s_pre[2] = y0;
        s_pre[3] = w;   s_pre[4] = h;  s_pre[5] = d;
    }
    __syncthreads();

    const int x = tx0 + threadIdx.x;
    const int y = ty0 + threadIdx.y;

    int idx = s_pre[0], x0 = s_pre[1], y0 = s_pre[2], w = s_pre[3], h = s_pre[4];
    const int d0 = s_pre[5];

    #pragma unroll 1
    for (int d = d0; d < MAXD; d++) {
        if (min(w, h) < 2) break;                  // leaf: region too small (checked pre-split)
        Node n = s_node[idx];
        if (idx & 1) {                             // vertical split (x axis)
            int lw = max(1, (int)floorf((float)w * n.ratio));
            if ((x - x0) < lw) { w = lw;           idx = n.child & 255; }
            else               { x0 += lw; w -= lw; idx = n.child >> 8; }
        } else {                                   // horizontal split (y axis)
            int th = max(1, (int)floorf((float)h * n.ratio));
            if ((y - y0) < th) { h = th;           idx = n.child & 255; }
            else               { y0 += th; h -= th; idx = n.child >> 8; }
        }
    }

    float4 c = s_col[idx];
    int p = y * WW + x;
    out[p]               = c.x;
    out[HH * WW + p]     = c.y;
    out[2 * HH * WW + p] = c.z;
}

extern "C" void kernel_launch(void* const* d_in, const int* in_sizes, int n_in,
                              void* d_out, int out_size) {
    const float* colors = (const float*)d_in[0];   // frame_colors   [64, 3]
    const float* sel    = (const float*)d_in[1];   // frame_selection [64, 2, 64]
    const float* ratios = (const float*)d_in[2];   // split_ratios   [64]
    float* out = (float*)d_out;                    // [3, 2048, 2048] fp32

    k_children<<<1, 64>>>(sel);

    dim3 block(64, 4);
    dim3 grid(WW / 64, HH / 4);
    k_render<<<grid, block>>>(colors, ratios, out);
}

// round 2
// speedup vs baseline: 1.6505x; 1.6505x over previous
#include <cuda_runtime.h>
#include <math.h>

#define HH 2048
#define WW 2048
#define NF 64
#define MAXD 12

struct Node { float ratio; int child; };

__device__ int g_left[NF];
__device__ int g_right[NF];

// Kernel 1: warp-parallel argmax (first-max tie-break = strict >, lower index wins ties).
// 128 warps total: warp g handles (frame = g>>1, side = g&1).
__global__ void k_children(const float* __restrict__ sel) {
    int warp_g = (blockIdx.x * blockDim.x + threadIdx.x) >> 5;
    int lane   = threadIdx.x & 31;
    if (warp_g >= 2 * NF) return;
    int frame = warp_g >> 1;
    int side  = warp_g & 1;
    const float* row = sel + frame * 2 * NF + side * NF;

    float v0 = row[lane];
    float v1 = row[lane + 32];
    float v;  int i;
    if (v1 > v0) { v = v1; i = lane + 32; } else { v = v0; i = lane; }

    #pragma unroll
    for (int off = 16; off >= 1; off >>= 1) {
        float ov = __shfl_xor_sync(0xffffffffu, v, off);
        int   oi = __shfl_xor_sync(0xffffffffu, i, off);
        if (ov > v || (ov == v && oi < i)) { v = ov; i = oi; }
    }
    if (lane == 0) {
        if (side == 0) g_left[frame] = i; else g_right[frame] = i;
    }
}

// Kernel 2: per-pixel BSP descent.
// Block (32,8) -> tile 128 wide x 8 tall (each thread renders 4 consecutive x pixels).
// Thread 0 descends the tree while the split line doesn't cross the tile
// (block-uniform prefix); threads resume per-pixel, reusing the leaf rect
// across their 4 pixels (one descent covers the whole run unless a leaf
// boundary crosses it).
__global__ __launch_bounds__(256) void k_render(
    const float* __restrict__ colors,
    const float* __restrict__ ratios,
    float* __restrict__ out)
{
    __shared__ Node   s_node[NF];
    __shared__ float4 s_col[NF];
    __shared__ int    s_pre[6];   // idx, x0, y0, w, h, depth

    const int t = threadIdx.y * 32 + threadIdx.x;
    if (t < NF) {
        Node n; n.ratio = ratios[t]; n.child = g_left[t] | (g_right[t] << 8);
        s_node[t] = n;
        s_col[t] = make_float4(colors[t * 3], colors[t * 3 + 1], colors[t * 3 + 2], 0.f);
    }
    __syncthreads();

    const int tx0 = blockIdx.x * 128;
    const int ty0 = blockIdx.y * 8;

    if (t == 0) {
        int idx = 0, x0 = 0, y0 = 0, w = WW, h = HH, d = 0;
        while (d < MAXD && w >= 2 && h >= 2) {
            Node n = s_node[idx];
            if (idx & 1) {
                int lw = max(1, (int)floorf((float)w * n.ratio));
                int xs = x0 + lw;
                if (tx0 + 128 <= xs)     { w = lw;           idx = n.child & 255; }
                else if (tx0 >= xs)      { x0 = xs; w -= lw; idx = n.child >> 8;  }
                else break;
            } else {
                int th = max(1, (int)floorf((float)h * n.ratio));
                int ys = y0 + th;
                if (ty0 + 8 <= ys)       { h = th;           idx = n.child & 255; }
                else if (ty0 >= ys)      { y0 = ys; h -= th; idx = n.child >> 8;  }
                else break;
            }
            d++;
        }
        s_pre[0] = idx; s_pre[1] = x0; s_pre[2] = y0;
        s_pre[3] = w;   s_pre[4] = h;  s_pre[5] = d;
    }
    __syncthreads();

    const int xbase = tx0 + threadIdx.x * 4;
    const int y     = ty0 + threadIdx.y;

    const int pidx = s_pre[0], px0 = s_pre[1], py0 = s_pre[2];
    const int pw = s_pre[3], ph = s_pre[4], d0 = s_pre[5];

    float r[4], g[4], b[4];
    int cur_reach = -1;           // exclusive x end of current leaf rect
    float4 col = make_float4(0.f, 0.f, 0.f, 0.f);

    #pragma unroll
    for (int q = 0; q < 4; q++) {
        int xq = xbase + q;
        if (xq >= cur_reach) {
            // fresh descent for pixel (xq, y) from the tile-uniform prefix state
            int idx = pidx, x0 = px0, y0 = py0, w = pw, h = ph;
            #pragma unroll 1
            for (int d = d0; d < MAXD; d++) {
                if (min(w, h) < 2) break;
                Node n = s_node[idx];
                if (idx & 1) {                       // vertical split (x axis)
                    int lw = max(1, (int)floorf((float)w * n.ratio));
                    if ((xq - x0) < lw) { w = lw;            idx = n.child & 255; }
                    else                { x0 += lw; w -= lw; idx = n.child >> 8;  }
                } else {                             // horizontal split (y axis)
                    int th = max(1, (int)floorf((float)h * n.ratio));
                    if ((y - y0) < th) { h = th;            idx = n.child & 255; }
                    else               { y0 += th; h -= th; idx = n.child >> 8;  }
                }
            }
            col = s_col[idx];
            cur_reach = x0 + w;    // all pixels with this y in [x0, x0+w) share this leaf
        }
        r[q] = col.x; g[q] = col.y; b[q] = col.z;
    }

    const int p = y * WW + xbase;
    *reinterpret_cast<float4*>(out + p)               = make_float4(r[0], r[1], r[2], r[3]);
    *reinterpret_cast<float4*>(out + HH * WW + p)     = make_float4(g[0], g[1], g[2], g[3]);
    *reinterpret_cast<float4*>(out + 2 * HH * WW + p) = make_float4(b[0], b[1], b[2], b[3]);
}

extern "C" void kernel_launch(void* const* d_in, const int* in_sizes, int n_in,
                              void* d_out, int out_size) {
    const float* colors = (const float*)d_in[0];   // frame_colors    [64, 3]
    const float* sel    = (const float*)d_in[1];   // frame_selection [64, 2, 64]
    const float* ratios = (const float*)d_in[2];   // split_ratios    [64]
    float* out = (float*)d_out;                    // [3, 2048, 2048] fp32

    k_children<<<16, 256>>>(sel);                  // 128 warps, one per argmax

    dim3 block(32, 8);
    dim3 grid(WW / 128, HH / 8);
    k_render<<<grid, block>>>(colors, ratios, out);
}